// round 3
// baseline (speedup 1.0000x reference)
#include <cuda_runtime.h>
#include <cstdint>

#define B_ 4
#define S_ 2048
#define D_ 1024
#define H_ 16
#define DK_ 64
#define M_ (B_ * S_)   // 8192

// Scratch (device globals — no allocation allowed)
__device__ float g_q[M_ * D_];     // [B,H,S,DK] tf32, q pre-scaled by 0.125*log2e
__device__ float g_k[M_ * D_];     // [B,H,S,DK] tf32
__device__ float g_v[M_ * D_];     // [B,H,S,DK] tf32
__device__ float g_x[M_ * D_];     // [B,S,D] attention out, tf32-rounded
__device__ float g_rq[M_ * D_];    // tf32-rounded copies of raw inputs
__device__ float g_rk[M_ * D_];
__device__ float g_rv[M_ * D_];
__device__ float g_rwq[D_ * D_];
__device__ float g_rwk[D_ * D_];
__device__ float g_rwv[D_ * D_];
__device__ float g_rwo[D_ * D_];
__device__ int   g_mflag[16 * 32];

__device__ __forceinline__ float to_tf32(float x) {
    float r;
    asm("cvt.rna.tf32.f32 %0, %1;" : "=f"(r) : "f"(x));
    return r;
}

__device__ __forceinline__ void mma8(float c[4], float a0, float a1, float a2, float a3,
                                     float b0, float b1) {
    asm volatile(
        "mma.sync.aligned.m16n8k8.row.col.f32.tf32.tf32.f32 "
        "{%0,%1,%2,%3}, {%4,%5,%6,%7}, {%8,%9}, {%0,%1,%2,%3};"
        : "+f"(c[0]), "+f"(c[1]), "+f"(c[2]), "+f"(c[3])
        : "r"(__float_as_uint(a0)), "r"(__float_as_uint(a1)),
          "r"(__float_as_uint(a2)), "r"(__float_as_uint(a3)),
          "r"(__float_as_uint(b0)), "r"(__float_as_uint(b1)));
}

__device__ __forceinline__ uint32_t smem_u32(const void* p) {
    return (uint32_t)__cvta_generic_to_shared(p);
}
__device__ __forceinline__ void cp_async16(uint32_t dst, const float* src) {
    asm volatile("cp.async.ca.shared.global [%0], [%1], 16;" :: "r"(dst), "l"(src));
}
__device__ __forceinline__ void cp_async4(uint32_t dst, const float* src) {
    asm volatile("cp.async.ca.shared.global [%0], [%1], 4;" :: "r"(dst), "l"(src));
}
#define CP_COMMIT() asm volatile("cp.async.commit_group;")
#define CP_WAIT1()  asm volatile("cp.async.wait_group 1;")

// ---------------------------------------------------------------------------
// tf32 rounding prepass (inputs are tf32-rounded once; GEMMs then use cp.async)
// ---------------------------------------------------------------------------
__global__ __launch_bounds__(256) void round_kernel(
    const float* __restrict__ q, const float* __restrict__ k, const float* __restrict__ v,
    const float* __restrict__ wq, const float* __restrict__ wk,
    const float* __restrict__ wv, const float* __restrict__ wo)
{
    const int which = blockIdx.y;
    const float* src;
    float* dst;
    int n4;
    if (which < 3) {
        n4 = M_ * D_ / 4;
        src = (which == 0) ? q : (which == 1) ? k : v;
        dst = (which == 0) ? g_rq : (which == 1) ? g_rk : g_rv;
    } else {
        n4 = D_ * D_ / 4;
        src = (which == 3) ? wq : (which == 4) ? wk : (which == 5) ? wv : wo;
        dst = (which == 3) ? g_rwq : (which == 4) ? g_rwk : (which == 5) ? g_rwv : g_rwo;
    }
    const int stride = gridDim.x * blockDim.x;
    for (int i = blockIdx.x * blockDim.x + threadIdx.x; i < n4; i += stride) {
        float4 t = ((const float4*)src)[i];
        ((float4*)dst)[i] =
            make_float4(to_tf32(t.x), to_tf32(t.y), to_tf32(t.z), to_tf32(t.w));
    }
}

// ---------------------------------------------------------------------------
// tf32 tensor-core GEMM, 3-stage cp.async pipeline.
// out[m,n] = sum_k X[m,k]*W[n,k] + bias[n].  BM=BN=128, BK=16, 256 thr.
// Smem per tensor per stage: 128 rows x stride 20 (conflict-free fragments).
// ---------------------------------------------------------------------------
#define GSTG 2560              // 128*20 floats per stage per tensor
#define GEMM_SMEM_BYTES (2 * 3 * GSTG * 4)

template <bool SPLIT>
__device__ __forceinline__ void gemm_tc(
    float* As, float* Bs,
    const float* __restrict__ X, const float* __restrict__ W,
    const float* __restrict__ bias, float* __restrict__ out, float scale)
{
    const int tid = threadIdx.x;
    const int lane = tid & 31, wid = tid >> 5;
    const int g = lane >> 2, tg = lane & 3;
    const int wm = wid >> 1, wn = wid & 1;
    const int m0 = blockIdx.y * 128, n0 = blockIdx.x * 128;

    const uint32_t AsU = smem_u32(As), BsU = smem_u32(Bs);
    const int lr = tid >> 1;            // row 0..127
    const int lsg = (tid & 1) * 8;      // first float of this thread's 8-float half

    const float* xrow = X + (long long)(m0 + lr) * D_ + lsg;
    const float* wrow = W + (long long)(n0 + lr) * D_ + lsg;
    const uint32_t adst = AsU + (uint32_t)(lr * 20 + lsg) * 4;
    const uint32_t bdst = BsU + (uint32_t)(lr * 20 + lsg) * 4;

#define G_ISSUE(s, kb)                                        \
    do {                                                      \
        const float* xs = xrow + (kb) * 16;                   \
        const float* ws = wrow + (kb) * 16;                   \
        const uint32_t so = (uint32_t)((s) * GSTG) * 4;       \
        cp_async16(adst + so, xs);                            \
        cp_async16(adst + so + 16, xs + 4);                   \
        cp_async16(bdst + so, ws);                            \
        cp_async16(bdst + so + 16, ws + 4);                   \
    } while (0)

    float acc[2][8][4];
#pragma unroll
    for (int mt = 0; mt < 2; mt++)
#pragma unroll
        for (int nt = 0; nt < 8; nt++)
#pragma unroll
            for (int i = 0; i < 4; i++) acc[mt][nt][i] = 0.0f;

    G_ISSUE(0, 0);
    CP_COMMIT();
    G_ISSUE(1, 1);
    CP_COMMIT();

    for (int it = 0; it < 64; it++) {
        CP_WAIT1();
        __syncthreads();
        int nx = it + 2;
        if (nx >= 64) nx -= 64;          // wrap (harmless redundant loads at tail)
        G_ISSUE((it + 2) % 3, nx);
        CP_COMMIT();

        const float* Ab = As + (it % 3) * GSTG;
        const float* Bb = Bs + (it % 3) * GSTG;
#pragma unroll
        for (int kk = 0; kk < 2; kk++) {
            const int kb = kk * 8 + tg;
            float a[2][4];
#pragma unroll
            for (int mt = 0; mt < 2; mt++) {
                const float* Ap = &Ab[(wm * 32 + mt * 16 + g) * 20 + kb];
                a[mt][0] = Ap[0];
                a[mt][2] = Ap[4];
                a[mt][1] = Ap[8 * 20];
                a[mt][3] = Ap[8 * 20 + 4];
            }
#pragma unroll
            for (int nt = 0; nt < 8; nt++) {
                const float* Bp = &Bb[(wn * 64 + nt * 8 + g) * 20 + kb];
                const float b0 = Bp[0], b1 = Bp[4];
                mma8(acc[0][nt], a[0][0], a[0][1], a[0][2], a[0][3], b0, b1);
                mma8(acc[1][nt], a[1][0], a[1][1], a[1][2], a[1][3], b0, b1);
            }
        }
    }
#undef G_ISSUE

    // epilogue
#pragma unroll
    for (int mt = 0; mt < 2; mt++) {
        const int r0 = m0 + wm * 32 + mt * 16 + g;
#pragma unroll
        for (int nt = 0; nt < 8; nt++) {
            const int c = n0 + wn * 64 + nt * 8 + tg * 2;
            const float bv0 = bias[c], bv1 = bias[c + 1];
            float v00 = acc[mt][nt][0] + bv0, v01 = acc[mt][nt][1] + bv1;
            float v10 = acc[mt][nt][2] + bv0, v11 = acc[mt][nt][3] + bv1;
            if (SPLIT) {
                v00 = to_tf32(v00 * scale); v01 = to_tf32(v01 * scale);
                v10 = to_tf32(v10 * scale); v11 = to_tf32(v11 * scale);
                const int h = c >> 6, dk = c & 63;
                const int bb = r0 >> 11, ss = r0 & 2047;
                float* o0 = &out[(((bb * H_ + h) * S_) + ss) * DK_ + dk];
                *(float2*)o0 = make_float2(v00, v01);
                *(float2*)(o0 + 8 * DK_) = make_float2(v10, v11);
            } else {
                *(float2*)&out[r0 * D_ + c] = make_float2(v00, v01);
                *(float2*)&out[(r0 + 8) * D_ + c] = make_float2(v10, v11);
            }
        }
    }
}

// 0.125 * log2(e): folds both the 1/sqrt(DK) scale and the exp->exp2 conversion
#define QSCALE 0.1803368801111204f

__global__ __launch_bounds__(256) void qkv_kernel(
    const float* __restrict__ wq2, const float* __restrict__ bq,
    const float* __restrict__ bk, const float* __restrict__ bv)
{
    extern __shared__ __align__(16) float sm[];
    float* As = sm;
    float* Bs = sm + 3 * GSTG;
    (void)wq2;
    if (blockIdx.z == 0)      gemm_tc<true>(As, Bs, g_rq, g_rwq, bq, g_q, QSCALE);
    else if (blockIdx.z == 1) gemm_tc<true>(As, Bs, g_rk, g_rwk, bk, g_k, 1.0f);
    else                      gemm_tc<true>(As, Bs, g_rv, g_rwv, bv, g_v, 1.0f);
}

__global__ __launch_bounds__(256) void oproj_kernel(
    const float* __restrict__ bo, float* __restrict__ out)
{
    extern __shared__ __align__(16) float sm[];
    float* As = sm;
    float* Bs = sm + 3 * GSTG;
    gemm_tc<false>(As, Bs, g_x, g_rwo, bo, out, 1.0f);
}

// ---------------------------------------------------------------------------
// Mask prescan: flag[qt][kt] = 1 iff mask all-nonzero in the 128x64 tile.
// ---------------------------------------------------------------------------
__global__ __launch_bounds__(256) void mask_scan_kernel(const int* __restrict__ mask)
{
    const int qt = blockIdx.x, kt = blockIdx.y;
    const int tid = threadIdx.x;
    const int r = tid >> 1, h = tid & 1;
    const int* p = mask + (qt * 128 + r) * S_ + kt * 64 + h * 32;
    bool ok = true;
#pragma unroll
    for (int j = 0; j < 8; j++) {
        int4 v = *(const int4*)(p + j * 4);
        ok &= (v.x != 0) & (v.y != 0) & (v.z != 0) & (v.w != 0);
    }
    const int all = __syncthreads_and((int)ok);
    if (tid == 0) g_mflag[qt * 32 + kt] = all;
}

// ---------------------------------------------------------------------------
// Flash attention, tf32 mma, 3-stage cp.async K/V pipeline, base-2 softmax.
// Block: one (b,h) x 128 q-rows. 8 warps, warp w owns q-rows w*16..w*16+15.
// Perm layout p(c) = (c&3)*18 + (c>>2), row stride 72.
// ---------------------------------------------------------------------------
#define QS_N (128 * 72)
#define KV_STG (64 * 72)
#define PS_N (128 * 72)
#define ATTN_SMEM_BYTES ((QS_N + 3 * KV_STG + 3 * KV_STG + PS_N) * 4)

__global__ __launch_bounds__(256) void attn_kernel(const int* __restrict__ mask)
{
    extern __shared__ __align__(16) float sm[];
    float* Qs = sm;
    float* Ks = Qs + QS_N;
    float* Vt = Ks + 3 * KV_STG;
    float* Ps = Vt + 3 * KV_STG;

    const int tid = threadIdx.x;
    const int lane = tid & 31, wid = tid >> 5;
    const int g = lane >> 2, tg = lane & 3;
    const int w16 = wid * 16;
    const int q0 = blockIdx.x * 128;
    const int bh = blockIdx.y;

    const float* Qg = g_q + bh * S_ * DK_;
    const float* Kg = g_k + bh * S_ * DK_;
    const float* Vg = g_v + bh * S_ * DK_;

    const uint32_t KsU = smem_u32(Ks), VtU = smem_u32(Vt);
    const int lrr = tid >> 2, qd = tid & 3;
    const int pkr = (lrr & 3) * 18 + (lrr >> 2);

#define KV_ISSUE(s, ktile)                                                      \
    do {                                                                        \
        const float* pk = Kg + ((ktile) * 64 + lrr) * DK_ + qd * 16;            \
        const float* pv = Vg + ((ktile) * 64 + lrr) * DK_ + qd * 16;            \
        const uint32_t kb = KsU + (uint32_t)((s) * KV_STG + lrr * 72) * 4;      \
        const uint32_t vb = VtU + (uint32_t)((s) * KV_STG) * 4;                 \
        _Pragma("unroll")                                                       \
        for (int j = 0; j < 4; j++) {                                           \
            _Pragma("unroll")                                                   \
            for (int e = 0; e < 4; e++) {                                       \
                cp_async4(kb + (uint32_t)(e * 18 + qd * 4 + j) * 4,             \
                          pk + j * 4 + e);                                      \
                cp_async4(vb + (uint32_t)((qd * 16 + j * 4 + e) * 72 + pkr) * 4,\
                          pv + j * 4 + e);                                      \
            }                                                                   \
        }                                                                       \
    } while (0)

    // Load Q tile (128x64) into perm layout, once.
    {
        const int r = tid >> 1, hf = tid & 1;
        const float* p = Qg + (q0 + r) * DK_ + hf * 32;
        float* dst = Qs + r * 72;
#pragma unroll
        for (int j = 0; j < 8; j++) {
            float4 v = *(const float4*)(p + j * 4);
            const int pg = hf * 8 + j;
            dst[pg] = v.x; dst[18 + pg] = v.y; dst[36 + pg] = v.z; dst[54 + pg] = v.w;
        }
    }

    KV_ISSUE(0, 0);
    CP_COMMIT();
    KV_ISSUE(1, 1);
    CP_COMMIT();

    float mrow0 = -1e30f, mrow1 = -1e30f;
    float lrow0 = 0.0f, lrow1 = 0.0f;
    float o[8][4];
#pragma unroll
    for (int nt = 0; nt < 8; nt++)
#pragma unroll
        for (int i = 0; i < 4; i++) o[nt][i] = 0.0f;

    const int pb = ((tg * 2) & 3) * 18 + (tg >> 1);
    const int fA = tg * 18;

    for (int kt = 0; kt < 32; kt++) {
        CP_WAIT1();
        __syncthreads();
        KV_ISSUE((kt + 2) % 3, (kt + 2) & 31);
        CP_COMMIT();

        const float* Ksb = Ks + (kt % 3) * KV_STG;
        const float* Vtb = Vt + (kt % 3) * KV_STG;

        // S = Qs @ Ks^T  (warp: 16x64)
        float s[8][4];
#pragma unroll
        for (int nt = 0; nt < 8; nt++)
#pragma unroll
            for (int i = 0; i < 4; i++) s[nt][i] = 0.0f;

#pragma unroll
        for (int kk = 0; kk < 8; kk++) {
            const float2 aA = *(const float2*)&Qs[(w16 + g) * 72 + fA + kk * 2];
            const float2 aB = *(const float2*)&Qs[(w16 + 8 + g) * 72 + fA + kk * 2];
#pragma unroll
            for (int nt = 0; nt < 8; nt++) {
                const float2 bv = *(const float2*)&Ksb[(nt * 8 + g) * 72 + fA + kk * 2];
                mma8(s[nt], aA.x, aB.x, aA.y, aB.y, bv.x, bv.y);
            }
        }

        // Mask (rare path)
        if (!g_mflag[blockIdx.x * 32 + kt]) {
            const int k0 = kt * 64;
            const int* mp0 = mask + (q0 + w16 + g) * S_ + k0 + tg * 2;
            const int* mp1 = mp0 + 8 * S_;
#pragma unroll
            for (int nt = 0; nt < 8; nt++) {
                const int2 m0v = *(const int2*)(mp0 + nt * 8);
                const int2 m1v = *(const int2*)(mp1 + nt * 8);
                if (m0v.x == 0) s[nt][0] = -1e9f;
                if (m0v.y == 0) s[nt][1] = -1e9f;
                if (m1v.x == 0) s[nt][2] = -1e9f;
                if (m1v.y == 0) s[nt][3] = -1e9f;
            }
        }

        // Online softmax (base 2): rows g and g+8, reduce across quad lanes
        float mx0 = -1e30f, mx1 = -1e30f;
#pragma unroll
        for (int nt = 0; nt < 8; nt++) {
            mx0 = fmaxf(mx0, fmaxf(s[nt][0], s[nt][1]));
            mx1 = fmaxf(mx1, fmaxf(s[nt][2], s[nt][3]));
        }
        mx0 = fmaxf(mx0, __shfl_xor_sync(0xffffffffu, mx0, 1));
        mx0 = fmaxf(mx0, __shfl_xor_sync(0xffffffffu, mx0, 2));
        mx1 = fmaxf(mx1, __shfl_xor_sync(0xffffffffu, mx1, 1));
        mx1 = fmaxf(mx1, __shfl_xor_sync(0xffffffffu, mx1, 2));
        const float mn0 = fmaxf(mrow0, mx0);
        const float mn1 = fmaxf(mrow1, mx1);
        const float al0 = exp2f(mrow0 - mn0);
        const float al1 = exp2f(mrow1 - mn1);
        mrow0 = mn0; mrow1 = mn1;

        float sum0 = 0.0f, sum1 = 0.0f;
        float* P0 = &Ps[(w16 + g) * 72 + pb];
        float* P1 = &Ps[(w16 + 8 + g) * 72 + pb];
#pragma unroll
        for (int nt = 0; nt < 8; nt++) {
            const float p0 = exp2f(s[nt][0] - mn0);
            const float p1 = exp2f(s[nt][1] - mn0);
            const float p2 = exp2f(s[nt][2] - mn1);
            const float p3 = exp2f(s[nt][3] - mn1);
            sum0 += p0 + p1;
            sum1 += p2 + p3;
            P0[nt * 2] = to_tf32(p0);
            P0[nt * 2 + 18] = to_tf32(p1);
            P1[nt * 2] = to_tf32(p2);
            P1[nt * 2 + 18] = to_tf32(p3);
            o[nt][0] *= al0; o[nt][1] *= al0;
            o[nt][2] *= al1; o[nt][3] *= al1;
        }
        sum0 += __shfl_xor_sync(0xffffffffu, sum0, 1);
        sum0 += __shfl_xor_sync(0xffffffffu, sum0, 2);
        sum1 += __shfl_xor_sync(0xffffffffu, sum1, 1);
        sum1 += __shfl_xor_sync(0xffffffffu, sum1, 2);
        lrow0 = lrow0 * al0 + sum0;
        lrow1 = lrow1 * al1 + sum1;
        __syncwarp();

        // O += P @ V  (warp: 16x64)
#pragma unroll
        for (int kk = 0; kk < 8; kk++) {
            const float2 aA = *(const float2*)&Ps[(w16 + g) * 72 + fA + kk * 2];
            const float2 aB = *(const float2*)&Ps[(w16 + 8 + g) * 72 + fA + kk * 2];
#pragma unroll
            for (int nt = 0; nt < 8; nt++) {
                const float2 bv = *(const float2*)&Vtb[(nt * 8 + g) * 72 + fA + kk * 2];
                mma8(o[nt], aA.x, aB.x, aA.y, aB.y, bv.x, bv.y);
            }
        }
    }
#undef KV_ISSUE

    // Normalize, round to tf32 (consumed by cp.async oproj), store [B,S,D]
    const float inv0 = 1.0f / lrow0;
    const float inv1 = 1.0f / lrow1;
    const int bb = bh >> 4, h = bh & 15;
    const int r0 = q0 + w16 + g;
    float* O0 = &g_x[(bb * S_ + r0) * D_ + h * DK_ + tg * 2];
    float* O1 = O0 + 8 * D_;
#pragma unroll
    for (int nt = 0; nt < 8; nt++) {
        *(float2*)(O0 + nt * 8) =
            make_float2(to_tf32(o[nt][0] * inv0), to_tf32(o[nt][1] * inv0));
        *(float2*)(O1 + nt * 8) =
            make_float2(to_tf32(o[nt][2] * inv1), to_tf32(o[nt][3] * inv1));
    }
}

// ---------------------------------------------------------------------------
extern "C" void kernel_launch(void* const* d_in, const int* in_sizes, int n_in,
                              void* d_out, int out_size)
{
    (void)in_sizes; (void)n_in; (void)out_size;
    const float* q    = (const float*)d_in[0];
    const float* k    = (const float*)d_in[1];
    const float* v    = (const float*)d_in[2];
    const int*   mask = (const int*)d_in[3];
    const float* wq   = (const float*)d_in[4];
    const float* bq   = (const float*)d_in[5];
    const float* wk   = (const float*)d_in[6];
    const float* bk   = (const float*)d_in[7];
    const float* wv   = (const float*)d_in[8];
    const float* bv   = (const float*)d_in[9];
    const float* wo   = (const float*)d_in[10];
    const float* bo   = (const float*)d_in[11];
    float* out = (float*)d_out;

    static bool attrs_set = false;
    if (!attrs_set) {
        cudaFuncSetAttribute(qkv_kernel, cudaFuncAttributeMaxDynamicSharedMemorySize,
                             GEMM_SMEM_BYTES);
        cudaFuncSetAttribute(oproj_kernel, cudaFuncAttributeMaxDynamicSharedMemorySize,
                             GEMM_SMEM_BYTES);
        cudaFuncSetAttribute(attn_kernel, cudaFuncAttributeMaxDynamicSharedMemorySize,
                             ATTN_SMEM_BYTES);
        attrs_set = true;
    }

    // tf32 rounding prepass
    dim3 grd(1024, 7);
    round_kernel<<<grd, 256>>>(q, k, v, wq, wk, wv, wo);

    // QKV projections
    dim3 gqkv(D_ / 128, M_ / 128, 3);
    qkv_kernel<<<gqkv, 256, GEMM_SMEM_BYTES>>>(wq, bq, bk, bv);

    // Mask prescan
    dim3 gms(16, 32);
    mask_scan_kernel<<<gms, 256>>>(mask);

    // Attention
    dim3 gattn(S_ / 128, B_ * H_);
    attn_kernel<<<gattn, 256, ATTN_SMEM_BYTES>>>(mask);

    // Output projection
    dim3 gop(D_ / 128, M_ / 128);
    oproj_kernel<<<gop, 256, GEMM_SMEM_BYTES>>>(bo, out);
}

// round 5
// speedup vs baseline: 1.4884x; 1.4884x over previous
#include <cuda_runtime.h>
#include <cstdint>

#define B_ 4
#define S_ 2048
#define D_ 1024
#define H_ 16
#define DK_ 64
#define M_ (B_ * S_)   // 8192

// Scratch (device globals — no allocation allowed)
__device__ float g_q[M_ * D_];     // [B,H,S,DK] tf32, q pre-scaled by 0.125*log2e
__device__ float g_k[M_ * D_];     // [B,H,S,DK] tf32
__device__ float g_v[M_ * D_];     // [B,H,S,DK] tf32
__device__ float g_vT[M_ * D_];    // [B,H,DK,S] tf32 (V transposed per head)
__device__ float g_x[M_ * D_];     // [B,S,D] attention out, tf32-rounded
__device__ float g_rq[M_ * D_];    // tf32-rounded copies of raw inputs
__device__ float g_rk[M_ * D_];
__device__ float g_rv[M_ * D_];
__device__ float g_rwq[D_ * D_];
__device__ float g_rwk[D_ * D_];
__device__ float g_rwv[D_ * D_];
__device__ float g_rwo[D_ * D_];
__device__ int   g_mflag[16 * 32];

__device__ __forceinline__ float to_tf32(float x) {
    float r;
    asm("cvt.rna.tf32.f32 %0, %1;" : "=f"(r) : "f"(x));
    return r;
}

__device__ __forceinline__ void mma8(float c[4], float a0, float a1, float a2, float a3,
                                     float b0, float b1) {
    asm volatile(
        "mma.sync.aligned.m16n8k8.row.col.f32.tf32.tf32.f32 "
        "{%0,%1,%2,%3}, {%4,%5,%6,%7}, {%8,%9}, {%0,%1,%2,%3};"
        : "+f"(c[0]), "+f"(c[1]), "+f"(c[2]), "+f"(c[3])
        : "r"(__float_as_uint(a0)), "r"(__float_as_uint(a1)),
          "r"(__float_as_uint(a2)), "r"(__float_as_uint(a3)),
          "r"(__float_as_uint(b0)), "r"(__float_as_uint(b1)));
}

__device__ __forceinline__ uint32_t smem_u32(const void* p) {
    return (uint32_t)__cvta_generic_to_shared(p);
}
__device__ __forceinline__ void cp_async16(uint32_t dst, const float* src) {
    asm volatile("cp.async.ca.shared.global [%0], [%1], 16;" :: "r"(dst), "l"(src));
}
#define CP_COMMIT() asm volatile("cp.async.commit_group;")
#define CP_WAIT1()  asm volatile("cp.async.wait_group 1;")
#define CP_WAIT0()  asm volatile("cp.async.wait_group 0;")

// ---------------------------------------------------------------------------
// tf32 rounding prepass
// ---------------------------------------------------------------------------
__global__ __launch_bounds__(256) void round_kernel(
    const float* __restrict__ q, const float* __restrict__ k, const float* __restrict__ v,
    const float* __restrict__ wq, const float* __restrict__ wk,
    const float* __restrict__ wv, const float* __restrict__ wo)
{
    const int which = blockIdx.y;
    const float* src;
    float* dst;
    int n4;
    if (which < 3) {
        n4 = M_ * D_ / 4;
        src = (which == 0) ? q : (which == 1) ? k : v;
        dst = (which == 0) ? g_rq : (which == 1) ? g_rk : g_rv;
    } else {
        n4 = D_ * D_ / 4;
        src = (which == 3) ? wq : (which == 4) ? wk : (which == 5) ? wv : wo;
        dst = (which == 3) ? g_rwq : (which == 4) ? g_rwk : (which == 5) ? g_rwv : g_rwo;
    }
    const int stride = gridDim.x * blockDim.x;
    for (int i = blockIdx.x * blockDim.x + threadIdx.x; i < n4; i += stride) {
        float4 t = ((const float4*)src)[i];
        ((float4*)dst)[i] =
            make_float4(to_tf32(t.x), to_tf32(t.y), to_tf32(t.z), to_tf32(t.w));
    }
}

// ---------------------------------------------------------------------------
// V transpose: g_v [bh][s][dk] -> g_vT [bh][dk][s]
// ---------------------------------------------------------------------------
__global__ __launch_bounds__(256) void vtrans_kernel()
{
    __shared__ float t[32][33];
    const int s0 = blockIdx.x * 32, d0 = blockIdx.y * 32, bh = blockIdx.z;
    const float* src = g_v + bh * S_ * DK_;
    float* dst = g_vT + bh * DK_ * S_;
    const int tx = threadIdx.x & 31, ty = threadIdx.x >> 5;
#pragma unroll
    for (int i = 0; i < 4; i++)
        t[ty + i * 8][tx] = src[(s0 + ty + i * 8) * DK_ + d0 + tx];
    __syncthreads();
#pragma unroll
    for (int i = 0; i < 4; i++)
        dst[(d0 + ty + i * 8) * S_ + s0 + tx] = t[tx][ty + i * 8];
}

// ---------------------------------------------------------------------------
// tf32 tensor-core GEMM, 3-stage cp.async pipeline.
// out[m,n] = sum_k X[m,k]*W[n,k] + bias[n].  BM=BN=128, BK=16, 256 thr.
// ---------------------------------------------------------------------------
#define GSTG 2560              // 128*20 floats per stage per tensor
#define GEMM_SMEM_BYTES (2 * 3 * GSTG * 4)

template <bool SPLIT>
__device__ __forceinline__ void gemm_tc(
    float* As, float* Bs,
    const float* __restrict__ X, const float* __restrict__ W,
    const float* __restrict__ bias, float* __restrict__ out, float scale)
{
    const int tid = threadIdx.x;
    const int lane = tid & 31, wid = tid >> 5;
    const int g = lane >> 2, tg = lane & 3;
    const int wm = wid >> 1, wn = wid & 1;
    const int m0 = blockIdx.y * 128, n0 = blockIdx.x * 128;

    const uint32_t AsU = smem_u32(As), BsU = smem_u32(Bs);
    const int lr = tid >> 1;
    const int lsg = (tid & 1) * 8;

    const float* xrow = X + (long long)(m0 + lr) * D_ + lsg;
    const float* wrow = W + (long long)(n0 + lr) * D_ + lsg;
    const uint32_t adst = AsU + (uint32_t)(lr * 20 + lsg) * 4;
    const uint32_t bdst = BsU + (uint32_t)(lr * 20 + lsg) * 4;

#define G_ISSUE(s, kb)                                        \
    do {                                                      \
        const float* xs = xrow + (kb) * 16;                   \
        const float* ws = wrow + (kb) * 16;                   \
        const uint32_t so = (uint32_t)((s) * GSTG) * 4;       \
        cp_async16(adst + so, xs);                            \
        cp_async16(adst + so + 16, xs + 4);                   \
        cp_async16(bdst + so, ws);                            \
        cp_async16(bdst + so + 16, ws + 4);                   \
    } while (0)

    float acc[2][8][4];
#pragma unroll
    for (int mt = 0; mt < 2; mt++)
#pragma unroll
        for (int nt = 0; nt < 8; nt++)
#pragma unroll
            for (int i = 0; i < 4; i++) acc[mt][nt][i] = 0.0f;

    G_ISSUE(0, 0);
    CP_COMMIT();
    G_ISSUE(1, 1);
    CP_COMMIT();

    for (int it = 0; it < 64; it++) {
        CP_WAIT1();
        __syncthreads();
        int nx = it + 2;
        if (nx >= 64) nx -= 64;
        G_ISSUE((it + 2) % 3, nx);
        CP_COMMIT();

        const float* Ab = As + (it % 3) * GSTG;
        const float* Bb = Bs + (it % 3) * GSTG;
#pragma unroll
        for (int kk = 0; kk < 2; kk++) {
            const int kb = kk * 8 + tg;
            float a[2][4];
#pragma unroll
            for (int mt = 0; mt < 2; mt++) {
                const float* Ap = &Ab[(wm * 32 + mt * 16 + g) * 20 + kb];
                a[mt][0] = Ap[0];
                a[mt][2] = Ap[4];
                a[mt][1] = Ap[8 * 20];
                a[mt][3] = Ap[8 * 20 + 4];
            }
#pragma unroll
            for (int nt = 0; nt < 8; nt++) {
                const float* Bp = &Bb[(wn * 64 + nt * 8 + g) * 20 + kb];
                const float b0 = Bp[0], b1 = Bp[4];
                mma8(acc[0][nt], a[0][0], a[0][1], a[0][2], a[0][3], b0, b1);
                mma8(acc[1][nt], a[1][0], a[1][1], a[1][2], a[1][3], b0, b1);
            }
        }
    }
#undef G_ISSUE

#pragma unroll
    for (int mt = 0; mt < 2; mt++) {
        const int r0 = m0 + wm * 32 + mt * 16 + g;
#pragma unroll
        for (int nt = 0; nt < 8; nt++) {
            const int c = n0 + wn * 64 + nt * 8 + tg * 2;
            const float bv0 = bias[c], bv1 = bias[c + 1];
            float v00 = acc[mt][nt][0] + bv0, v01 = acc[mt][nt][1] + bv1;
            float v10 = acc[mt][nt][2] + bv0, v11 = acc[mt][nt][3] + bv1;
            if (SPLIT) {
                v00 = to_tf32(v00 * scale); v01 = to_tf32(v01 * scale);
                v10 = to_tf32(v10 * scale); v11 = to_tf32(v11 * scale);
                const int h = c >> 6, dk = c & 63;
                const int bb = r0 >> 11, ss = r0 & 2047;
                float* o0 = &out[(((bb * H_ + h) * S_) + ss) * DK_ + dk];
                *(float2*)o0 = make_float2(v00, v01);
                *(float2*)(o0 + 8 * DK_) = make_float2(v10, v11);
            } else {
                *(float2*)&out[r0 * D_ + c] = make_float2(v00, v01);
                *(float2*)&out[(r0 + 8) * D_ + c] = make_float2(v10, v11);
            }
        }
    }
}

// 0.125 * log2(e)
#define QSCALE 0.1803368801111204f

__global__ __launch_bounds__(256, 2) void qkv_kernel(
    const float* __restrict__ bq, const float* __restrict__ bk,
    const float* __restrict__ bv)
{
    extern __shared__ __align__(16) float sm[];
    float* As = sm;
    float* Bs = sm + 3 * GSTG;
    if (blockIdx.z == 0)      gemm_tc<true>(As, Bs, g_rq, g_rwq, bq, g_q, QSCALE);
    else if (blockIdx.z == 1) gemm_tc<true>(As, Bs, g_rk, g_rwk, bk, g_k, 1.0f);
    else                      gemm_tc<true>(As, Bs, g_rv, g_rwv, bv, g_v, 1.0f);
}

__global__ __launch_bounds__(256, 2) void oproj_kernel(
    const float* __restrict__ bo, float* __restrict__ out)
{
    extern __shared__ __align__(16) float sm[];
    float* As = sm;
    float* Bs = sm + 3 * GSTG;
    gemm_tc<false>(As, Bs, g_x, g_rwo, bo, out, 1.0f);
}

// ---------------------------------------------------------------------------
// Mask prescan
// ---------------------------------------------------------------------------
__global__ __launch_bounds__(256) void mask_scan_kernel(const int* __restrict__ mask)
{
    const int qt = blockIdx.x, kt = blockIdx.y;
    const int tid = threadIdx.x;
    const int r = tid >> 1, h = tid & 1;
    const int* p = mask + (qt * 128 + r) * S_ + kt * 64 + h * 32;
    bool ok = true;
#pragma unroll
    for (int j = 0; j < 8; j++) {
        int4 v = *(const int4*)(p + j * 4);
        ok &= (v.x != 0) & (v.y != 0) & (v.z != 0) & (v.w != 0);
    }
    const int all = __syncthreads_and((int)ok);
    if (tid == 0) g_mflag[qt * 32 + kt] = all;
}

// ---------------------------------------------------------------------------
// Flash attention, tf32 mma, natural layouts, P in registers,
// double-buffered 16B cp.async K/V, base-2 softmax.
// ---------------------------------------------------------------------------
#define AST 72
#define ATQ (128 * AST)
#define ATKV (64 * AST)
#define ATTN_SMEM_BYTES ((ATQ + 4 * ATKV) * 4)   // 110592 B

__global__ __launch_bounds__(256) void attn_kernel(const int* __restrict__ mask)
{
    extern __shared__ __align__(16) float sm[];
    float* Qs = sm;
    float* Ks = sm + ATQ;            // 2 stages
    float* Vt = sm + ATQ + 2 * ATKV; // 2 stages (dk rows x kv cols)

    const int tid = threadIdx.x;
    const int lane = tid & 31, wid = tid >> 5;
    const int g = lane >> 2, tg = lane & 3;
    const int w16 = wid * 16;
    const int q0 = blockIdx.x * 128;
    const int bh = blockIdx.y;

    const float* Qg = g_q + bh * S_ * DK_;
    const float* Kg = g_k + bh * S_ * DK_;
    const float* Vg = g_vT + bh * DK_ * S_;

    const uint32_t QsU = smem_u32(Qs), KsU = smem_u32(Ks), VtU = smem_u32(Vt);
    const int r = tid >> 2, qd = tid & 3;

    // Q tile (128x64) via cp.async, natural layout
    {
        const int qr = tid >> 1, hf = tid & 1;
        const float* src = Qg + (q0 + qr) * DK_ + hf * 32;
        const uint32_t dst = QsU + (uint32_t)(qr * AST + hf * 32) * 4;
#pragma unroll
        for (int j = 0; j < 8; j++) cp_async16(dst + j * 16, src + j * 4);
    }

    // Each thread fills its full 16-float segment of K row r and V^T row r:
    // 4x cp.async16 per tensor (Round-4 bug: only 1 was issued).
#define KV_ISSUE(s, t)                                                          \
    do {                                                                        \
        const float* ksrc = Kg + ((t) * 64 + r) * DK_ + qd * 16;                \
        const float* vsrc = Vg + r * S_ + (t) * 64 + qd * 16;                   \
        const uint32_t kdst =                                                   \
            KsU + (uint32_t)((s) * ATKV + r * AST + qd * 16) * 4;               \
        const uint32_t vdst =                                                   \
            VtU + (uint32_t)((s) * ATKV + r * AST + qd * 16) * 4;               \
        _Pragma("unroll")                                                       \
        for (int j = 0; j < 4; j++) {                                           \
            cp_async16(kdst + j * 16, ksrc + j * 4);                            \
            cp_async16(vdst + j * 16, vsrc + j * 4);                            \
        }                                                                       \
    } while (0)

    KV_ISSUE(0, 0);
    CP_COMMIT();
    KV_ISSUE(1, 1);
    CP_COMMIT();

    float mrow0 = -1e30f, mrow1 = -1e30f;
    float lrow0 = 0.0f, lrow1 = 0.0f;
    float o[8][4];
#pragma unroll
    for (int nt = 0; nt < 8; nt++)
#pragma unroll
        for (int i = 0; i < 4; i++) o[nt][i] = 0.0f;

    for (int kt = 0; kt < 32; kt++) {
        CP_WAIT1();
        __syncthreads();
        const float* Ksb = Ks + (kt & 1) * ATKV;
        const float* Vtb = Vt + (kt & 1) * ATKV;

        // S = Q @ K^T (warp: 16x64)
        float s[8][4];
#pragma unroll
        for (int nt = 0; nt < 8; nt++)
#pragma unroll
            for (int i = 0; i < 4; i++) s[nt][i] = 0.0f;

#pragma unroll
        for (int kk = 0; kk < 8; kk++) {
            const float2 aA = *(const float2*)&Qs[(w16 + g) * AST + kk * 8 + tg * 2];
            const float2 aB = *(const float2*)&Qs[(w16 + 8 + g) * AST + kk * 8 + tg * 2];
#pragma unroll
            for (int nt = 0; nt < 8; nt++) {
                const float2 bv =
                    *(const float2*)&Ksb[(nt * 8 + g) * AST + kk * 8 + tg * 2];
                mma8(s[nt], aA.x, aB.x, aA.y, aB.y, bv.x, bv.y);
            }
        }

        // Mask (rare path)
        if (!g_mflag[blockIdx.x * 32 + kt]) {
            const int k0 = kt * 64;
            const int* mp0 = mask + (q0 + w16 + g) * S_ + k0 + tg * 2;
            const int* mp1 = mp0 + 8 * S_;
#pragma unroll
            for (int nt = 0; nt < 8; nt++) {
                const int2 m0v = *(const int2*)(mp0 + nt * 8);
                const int2 m1v = *(const int2*)(mp1 + nt * 8);
                if (m0v.x == 0) s[nt][0] = -1e9f;
                if (m0v.y == 0) s[nt][1] = -1e9f;
                if (m1v.x == 0) s[nt][2] = -1e9f;
                if (m1v.y == 0) s[nt][3] = -1e9f;
            }
        }

        // Online softmax (base 2); P stays in registers (s[])
        float mx0 = -1e30f, mx1 = -1e30f;
#pragma unroll
        for (int nt = 0; nt < 8; nt++) {
            mx0 = fmaxf(mx0, fmaxf(s[nt][0], s[nt][1]));
            mx1 = fmaxf(mx1, fmaxf(s[nt][2], s[nt][3]));
        }
        mx0 = fmaxf(mx0, __shfl_xor_sync(0xffffffffu, mx0, 1));
        mx0 = fmaxf(mx0, __shfl_xor_sync(0xffffffffu, mx0, 2));
        mx1 = fmaxf(mx1, __shfl_xor_sync(0xffffffffu, mx1, 1));
        mx1 = fmaxf(mx1, __shfl_xor_sync(0xffffffffu, mx1, 2));
        const float mn0 = fmaxf(mrow0, mx0);
        const float mn1 = fmaxf(mrow1, mx1);
        const float al0 = exp2f(mrow0 - mn0);
        const float al1 = exp2f(mrow1 - mn1);
        mrow0 = mn0; mrow1 = mn1;

        float sum0 = 0.0f, sum1 = 0.0f;
#pragma unroll
        for (int nt = 0; nt < 8; nt++) {
            const float p0 = exp2f(s[nt][0] - mn0);
            const float p1 = exp2f(s[nt][1] - mn0);
            const float p2 = exp2f(s[nt][2] - mn1);
            const float p3 = exp2f(s[nt][3] - mn1);
            sum0 += p0 + p1;
            sum1 += p2 + p3;
            s[nt][0] = to_tf32(p0);
            s[nt][1] = to_tf32(p1);
            s[nt][2] = to_tf32(p2);
            s[nt][3] = to_tf32(p3);
            o[nt][0] *= al0; o[nt][1] *= al0;
            o[nt][2] *= al1; o[nt][3] *= al1;
        }
        sum0 += __shfl_xor_sync(0xffffffffu, sum0, 1);
        sum0 += __shfl_xor_sync(0xffffffffu, sum0, 2);
        sum1 += __shfl_xor_sync(0xffffffffu, sum1, 1);
        sum1 += __shfl_xor_sync(0xffffffffu, sum1, 2);
        lrow0 = lrow0 * al0 + sum0;
        lrow1 = lrow1 * al1 + sum1;

        // O += P @ V. C-fragment of QK is the A-fragment of PV under the
        // same k-permutation used on the B side (kv cols 2tg,2tg+1).
#pragma unroll
        for (int kk = 0; kk < 8; kk++) {
#pragma unroll
            for (int nt = 0; nt < 8; nt++) {
                const float2 bv =
                    *(const float2*)&Vtb[(nt * 8 + g) * AST + kk * 8 + tg * 2];
                mma8(o[nt], s[kk][0], s[kk][2], s[kk][1], s[kk][3], bv.x, bv.y);
            }
        }

        __syncthreads();   // all warps done with stage (kt&1)
        KV_ISSUE(kt & 1, (kt + 2) & 31);   // wrap: last 2 iters load dead data
        CP_COMMIT();
    }
#undef KV_ISSUE

    CP_WAIT0();  // drain async copies before CTA exit

    // Normalize, round to tf32 (consumed via cp.async by oproj), store [B,S,D]
    const float inv0 = 1.0f / lrow0;
    const float inv1 = 1.0f / lrow1;
    const int bb = bh >> 4, h = bh & 15;
    const int r0 = q0 + w16 + g;
    float* O0 = &g_x[(bb * S_ + r0) * D_ + h * DK_ + tg * 2];
    float* O1 = O0 + 8 * D_;
#pragma unroll
    for (int nt = 0; nt < 8; nt++) {
        *(float2*)(O0 + nt * 8) =
            make_float2(to_tf32(o[nt][0] * inv0), to_tf32(o[nt][1] * inv0));
        *(float2*)(O1 + nt * 8) =
            make_float2(to_tf32(o[nt][2] * inv1), to_tf32(o[nt][3] * inv1));
    }
}

// ---------------------------------------------------------------------------
extern "C" void kernel_launch(void* const* d_in, const int* in_sizes, int n_in,
                              void* d_out, int out_size)
{
    (void)in_sizes; (void)n_in; (void)out_size;
    const float* q    = (const float*)d_in[0];
    const float* k    = (const float*)d_in[1];
    const float* v    = (const float*)d_in[2];
    const int*   mask = (const int*)d_in[3];
    const float* wq   = (const float*)d_in[4];
    const float* bq   = (const float*)d_in[5];
    const float* wk   = (const float*)d_in[6];
    const float* bk   = (const float*)d_in[7];
    const float* wv   = (const float*)d_in[8];
    const float* bv   = (const float*)d_in[9];
    const float* wo   = (const float*)d_in[10];
    const float* bo   = (const float*)d_in[11];
    float* out = (float*)d_out;

    static bool attrs_set = false;
    if (!attrs_set) {
        cudaFuncSetAttribute(qkv_kernel, cudaFuncAttributeMaxDynamicSharedMemorySize,
                             GEMM_SMEM_BYTES);
        cudaFuncSetAttribute(oproj_kernel, cudaFuncAttributeMaxDynamicSharedMemorySize,
                             GEMM_SMEM_BYTES);
        cudaFuncSetAttribute(attn_kernel, cudaFuncAttributeMaxDynamicSharedMemorySize,
                             ATTN_SMEM_BYTES);
        attrs_set = true;
    }

    // tf32 rounding prepass
    dim3 grd(1024, 7);
    round_kernel<<<grd, 256>>>(q, k, v, wq, wk, wv, wo);

    // QKV projections
    dim3 gqkv(D_ / 128, M_ / 128, 3);
    qkv_kernel<<<gqkv, 256, GEMM_SMEM_BYTES>>>(bq, bk, bv);

    // V transpose + mask prescan (independent, small)
    dim3 gvt(S_ / 32, DK_ / 32, B_ * H_);
    vtrans_kernel<<<gvt, 256>>>();
    dim3 gms(16, 32);
    mask_scan_kernel<<<gms, 256>>>(mask);

    // Attention
    dim3 gattn(S_ / 128, B_ * H_);
    attn_kernel<<<gattn, 256, ATTN_SMEM_BYTES>>>(mask);

    // Output projection
    dim3 gop(D_ / 128, M_ / 128);
    oproj_kernel<<<gop, 256, GEMM_SMEM_BYTES>>>(bo, out);
}

// round 6
// speedup vs baseline: 1.5080x; 1.0132x over previous
#include <cuda_runtime.h>
#include <cstdint>

#define B_ 4
#define S_ 2048
#define D_ 1024
#define H_ 16
#define DK_ 64
#define M_ (B_ * S_)   // 8192

// Scratch (device globals — no allocation allowed)
__device__ float g_q[M_ * D_];     // [B,H,S,DK] tf32, q pre-scaled by 0.125*log2e
__device__ float g_k[M_ * D_];     // [B,H,S,DK] tf32
__device__ float g_v[M_ * D_];     // [B,H,S,DK] tf32
__device__ float g_vT[M_ * D_];    // [B,H,DK,S] tf32 (V transposed per head)
__device__ float g_x[M_ * D_];     // [B,S,D] attention out, tf32-rounded
__device__ float g_rq[M_ * D_];    // tf32-rounded copies of raw inputs
__device__ float g_rk[M_ * D_];
__device__ float g_rv[M_ * D_];
__device__ float g_rwq[D_ * D_];
__device__ float g_rwk[D_ * D_];
__device__ float g_rwv[D_ * D_];
__device__ float g_rwo[D_ * D_];
__device__ int   g_mflag[16 * 32];

__device__ __forceinline__ float to_tf32(float x) {
    float r;
    asm("cvt.rna.tf32.f32 %0, %1;" : "=f"(r) : "f"(x));
    return r;
}

__device__ __forceinline__ void mma8(float c[4], float a0, float a1, float a2, float a3,
                                     float b0, float b1) {
    asm volatile(
        "mma.sync.aligned.m16n8k8.row.col.f32.tf32.tf32.f32 "
        "{%0,%1,%2,%3}, {%4,%5,%6,%7}, {%8,%9}, {%0,%1,%2,%3};"
        : "+f"(c[0]), "+f"(c[1]), "+f"(c[2]), "+f"(c[3])
        : "r"(__float_as_uint(a0)), "r"(__float_as_uint(a1)),
          "r"(__float_as_uint(a2)), "r"(__float_as_uint(a3)),
          "r"(__float_as_uint(b0)), "r"(__float_as_uint(b1)));
}

__device__ __forceinline__ uint32_t smem_u32(const void* p) {
    return (uint32_t)__cvta_generic_to_shared(p);
}
__device__ __forceinline__ void cp_async16(uint32_t dst, const float* src) {
    asm volatile("cp.async.ca.shared.global [%0], [%1], 16;" :: "r"(dst), "l"(src));
}
#define CP_COMMIT() asm volatile("cp.async.commit_group;")
#define CP_WAIT1()  asm volatile("cp.async.wait_group 1;")
#define CP_WAIT0()  asm volatile("cp.async.wait_group 0;")

// ---------------------------------------------------------------------------
// tf32 rounding prepass
// ---------------------------------------------------------------------------
__global__ __launch_bounds__(256) void round_kernel(
    const float* __restrict__ q, const float* __restrict__ k, const float* __restrict__ v,
    const float* __restrict__ wq, const float* __restrict__ wk,
    const float* __restrict__ wv, const float* __restrict__ wo)
{
    const int which = blockIdx.y;
    const float* src;
    float* dst;
    int n4;
    if (which < 3) {
        n4 = M_ * D_ / 4;
        src = (which == 0) ? q : (which == 1) ? k : v;
        dst = (which == 0) ? g_rq : (which == 1) ? g_rk : g_rv;
    } else {
        n4 = D_ * D_ / 4;
        src = (which == 3) ? wq : (which == 4) ? wk : (which == 5) ? wv : wo;
        dst = (which == 3) ? g_rwq : (which == 4) ? g_rwk : (which == 5) ? g_rwv : g_rwo;
    }
    const int stride = gridDim.x * blockDim.x;
    for (int i = blockIdx.x * blockDim.x + threadIdx.x; i < n4; i += stride) {
        float4 t = ((const float4*)src)[i];
        ((float4*)dst)[i] =
            make_float4(to_tf32(t.x), to_tf32(t.y), to_tf32(t.z), to_tf32(t.w));
    }
}

// ---------------------------------------------------------------------------
// V transpose: g_v [bh][s][dk] -> g_vT [bh][dk][s]
// ---------------------------------------------------------------------------
__global__ __launch_bounds__(256) void vtrans_kernel()
{
    __shared__ float t[32][33];
    const int s0 = blockIdx.x * 32, d0 = blockIdx.y * 32, bh = blockIdx.z;
    const float* src = g_v + bh * S_ * DK_;
    float* dst = g_vT + bh * DK_ * S_;
    const int tx = threadIdx.x & 31, ty = threadIdx.x >> 5;
#pragma unroll
    for (int i = 0; i < 4; i++)
        t[ty + i * 8][tx] = src[(s0 + ty + i * 8) * DK_ + d0 + tx];
    __syncthreads();
#pragma unroll
    for (int i = 0; i < 4; i++)
        dst[(d0 + ty + i * 8) * S_ + s0 + tx] = t[tx][ty + i * 8];
}

// ---------------------------------------------------------------------------
// tf32 tensor-core GEMM, 3-stage cp.async pipeline. (unchanged from R5)
// ---------------------------------------------------------------------------
#define GSTG 2560              // 128*20 floats per stage per tensor
#define GEMM_SMEM_BYTES (2 * 3 * GSTG * 4)

template <bool SPLIT>
__device__ __forceinline__ void gemm_tc(
    float* As, float* Bs,
    const float* __restrict__ X, const float* __restrict__ W,
    const float* __restrict__ bias, float* __restrict__ out, float scale)
{
    const int tid = threadIdx.x;
    const int lane = tid & 31, wid = tid >> 5;
    const int g = lane >> 2, tg = lane & 3;
    const int wm = wid >> 1, wn = wid & 1;
    const int m0 = blockIdx.y * 128, n0 = blockIdx.x * 128;

    const uint32_t AsU = smem_u32(As), BsU = smem_u32(Bs);
    const int lr = tid >> 1;
    const int lsg = (tid & 1) * 8;

    const float* xrow = X + (long long)(m0 + lr) * D_ + lsg;
    const float* wrow = W + (long long)(n0 + lr) * D_ + lsg;
    const uint32_t adst = AsU + (uint32_t)(lr * 20 + lsg) * 4;
    const uint32_t bdst = BsU + (uint32_t)(lr * 20 + lsg) * 4;

#define G_ISSUE(s, kb)                                        \
    do {                                                      \
        const float* xs = xrow + (kb) * 16;                   \
        const float* ws = wrow + (kb) * 16;                   \
        const uint32_t so = (uint32_t)((s) * GSTG) * 4;       \
        cp_async16(adst + so, xs);                            \
        cp_async16(adst + so + 16, xs + 4);                   \
        cp_async16(bdst + so, ws);                            \
        cp_async16(bdst + so + 16, ws + 4);                   \
    } while (0)

    float acc[2][8][4];
#pragma unroll
    for (int mt = 0; mt < 2; mt++)
#pragma unroll
        for (int nt = 0; nt < 8; nt++)
#pragma unroll
            for (int i = 0; i < 4; i++) acc[mt][nt][i] = 0.0f;

    G_ISSUE(0, 0);
    CP_COMMIT();
    G_ISSUE(1, 1);
    CP_COMMIT();

    for (int it = 0; it < 64; it++) {
        CP_WAIT1();
        __syncthreads();
        int nx = it + 2;
        if (nx >= 64) nx -= 64;
        G_ISSUE((it + 2) % 3, nx);
        CP_COMMIT();

        const float* Ab = As + (it % 3) * GSTG;
        const float* Bb = Bs + (it % 3) * GSTG;
#pragma unroll
        for (int kk = 0; kk < 2; kk++) {
            const int kb = kk * 8 + tg;
            float a[2][4];
#pragma unroll
            for (int mt = 0; mt < 2; mt++) {
                const float* Ap = &Ab[(wm * 32 + mt * 16 + g) * 20 + kb];
                a[mt][0] = Ap[0];
                a[mt][2] = Ap[4];
                a[mt][1] = Ap[8 * 20];
                a[mt][3] = Ap[8 * 20 + 4];
            }
#pragma unroll
            for (int nt = 0; nt < 8; nt++) {
                const float* Bp = &Bb[(wn * 64 + nt * 8 + g) * 20 + kb];
                const float b0 = Bp[0], b1 = Bp[4];
                mma8(acc[0][nt], a[0][0], a[0][1], a[0][2], a[0][3], b0, b1);
                mma8(acc[1][nt], a[1][0], a[1][1], a[1][2], a[1][3], b0, b1);
            }
        }
    }
#undef G_ISSUE

#pragma unroll
    for (int mt = 0; mt < 2; mt++) {
        const int r0 = m0 + wm * 32 + mt * 16 + g;
#pragma unroll
        for (int nt = 0; nt < 8; nt++) {
            const int c = n0 + wn * 64 + nt * 8 + tg * 2;
            const float bv0 = bias[c], bv1 = bias[c + 1];
            float v00 = acc[mt][nt][0] + bv0, v01 = acc[mt][nt][1] + bv1;
            float v10 = acc[mt][nt][2] + bv0, v11 = acc[mt][nt][3] + bv1;
            if (SPLIT) {
                v00 = to_tf32(v00 * scale); v01 = to_tf32(v01 * scale);
                v10 = to_tf32(v10 * scale); v11 = to_tf32(v11 * scale);
                const int h = c >> 6, dk = c & 63;
                const int bb = r0 >> 11, ss = r0 & 2047;
                float* o0 = &out[(((bb * H_ + h) * S_) + ss) * DK_ + dk];
                *(float2*)o0 = make_float2(v00, v01);
                *(float2*)(o0 + 8 * DK_) = make_float2(v10, v11);
            } else {
                *(float2*)&out[r0 * D_ + c] = make_float2(v00, v01);
                *(float2*)&out[(r0 + 8) * D_ + c] = make_float2(v10, v11);
            }
        }
    }
}

// 0.125 * log2(e)
#define QSCALE 0.1803368801111204f

__global__ __launch_bounds__(256, 2) void qkv_kernel(
    const float* __restrict__ bq, const float* __restrict__ bk,
    const float* __restrict__ bv)
{
    extern __shared__ __align__(16) float sm[];
    float* As = sm;
    float* Bs = sm + 3 * GSTG;
    if (blockIdx.z == 0)      gemm_tc<true>(As, Bs, g_rq, g_rwq, bq, g_q, QSCALE);
    else if (blockIdx.z == 1) gemm_tc<true>(As, Bs, g_rk, g_rwk, bk, g_k, 1.0f);
    else                      gemm_tc<true>(As, Bs, g_rv, g_rwv, bv, g_v, 1.0f);
}

__global__ __launch_bounds__(256, 2) void oproj_kernel(
    const float* __restrict__ bo, float* __restrict__ out)
{
    extern __shared__ __align__(16) float sm[];
    float* As = sm;
    float* Bs = sm + 3 * GSTG;
    gemm_tc<false>(As, Bs, g_x, g_rwo, bo, out, 1.0f);
}

// ---------------------------------------------------------------------------
// Mask prescan
// ---------------------------------------------------------------------------
__global__ __launch_bounds__(256) void mask_scan_kernel(const int* __restrict__ mask)
{
    const int qt = blockIdx.x, kt = blockIdx.y;
    const int tid = threadIdx.x;
    const int r = tid >> 1, h = tid & 1;
    const int* p = mask + (qt * 128 + r) * S_ + kt * 64 + h * 32;
    bool ok = true;
#pragma unroll
    for (int j = 0; j < 8; j++) {
        int4 v = *(const int4*)(p + j * 4);
        ok &= (v.x != 0) & (v.y != 0) & (v.z != 0) & (v.w != 0);
    }
    const int all = __syncthreads_and((int)ok);
    if (tid == 0) g_mflag[qt * 32 + kt] = all;
}

// ---------------------------------------------------------------------------
// Flash attention, tf32 mma, XOR-swizzled stride-64 smem (96KB -> 2 CTA/SM),
// P in registers, double-buffered 16B cp.async K/V, base-2 softmax.
// Swizzle: phys_col = col ^ ((row & 7) * 8). All fragment rows (w16+g,
// w16+8+g, nt*8+g) have row&7 == g, so frag offset = row*64 + 8*(kk^g) + tg*2.
// ---------------------------------------------------------------------------
#define ATQ (128 * 64)
#define ATKV (64 * 64)
#define ATTN_SMEM_BYTES ((ATQ + 4 * ATKV) * 4)   // 98304 B = 96KB

__global__ __launch_bounds__(256, 2) void attn_kernel(const int* __restrict__ mask)
{
    extern __shared__ __align__(16) float sm[];
    float* Qs = sm;
    float* Ks = sm + ATQ;            // 2 stages
    float* Vt = sm + ATQ + 2 * ATKV; // 2 stages (dk rows x kv cols)

    const int tid = threadIdx.x;
    const int lane = tid & 31, wid = tid >> 5;
    const int g = lane >> 2, tg = lane & 3;
    const int w16 = wid * 16;
    const int q0 = blockIdx.x * 128;
    const int bh = blockIdx.y;

    const float* Qg = g_q + bh * S_ * DK_;
    const float* Kg = g_k + bh * S_ * DK_;
    const float* Vg = g_vT + bh * DK_ * S_;

    const uint32_t QsU = smem_u32(Qs), KsU = smem_u32(Ks), VtU = smem_u32(Vt);
    const int r = tid >> 2, qd = tid & 3;
    const int rsw = (r & 7) * 8;     // swizzle term for loader row r

    // Q tile (128x64) via cp.async, swizzled layout
    {
        const int qr = tid >> 1, hf = tid & 1;
        const int qsw = (qr & 7) * 8;
        const float* src = Qg + (q0 + qr) * DK_ + hf * 32;
        const uint32_t dstb = QsU + (uint32_t)(qr * 64) * 4;
#pragma unroll
        for (int j = 0; j < 8; j++)
            cp_async16(dstb + (uint32_t)((hf * 32 + j * 4) ^ qsw) * 4, src + j * 4);
    }

#define KV_ISSUE(s, t)                                                          \
    do {                                                                        \
        const float* ksrc = Kg + ((t) * 64 + r) * DK_ + qd * 16;                \
        const float* vsrc = Vg + r * S_ + (t) * 64 + qd * 16;                   \
        const uint32_t kdb = KsU + (uint32_t)((s) * ATKV + r * 64) * 4;         \
        const uint32_t vdb = VtU + (uint32_t)((s) * ATKV + r * 64) * 4;         \
        _Pragma("unroll")                                                       \
        for (int j = 0; j < 4; j++) {                                           \
            const uint32_t co = (uint32_t)((qd * 16 + j * 4) ^ rsw) * 4;        \
            cp_async16(kdb + co, ksrc + j * 4);                                 \
            cp_async16(vdb + co, vsrc + j * 4);                                 \
        }                                                                       \
    } while (0)

    KV_ISSUE(0, 0);
    CP_COMMIT();
    KV_ISSUE(1, 1);
    CP_COMMIT();

    float mrow0 = -1e30f, mrow1 = -1e30f;
    float lrow0 = 0.0f, lrow1 = 0.0f;
    float o[8][4];
#pragma unroll
    for (int nt = 0; nt < 8; nt++)
#pragma unroll
        for (int i = 0; i < 4; i++) o[nt][i] = 0.0f;

    for (int kt = 0; kt < 32; kt++) {
        CP_WAIT1();
        __syncthreads();
        const float* Ksb = Ks + (kt & 1) * ATKV;
        const float* Vtb = Vt + (kt & 1) * ATKV;

        // S = Q @ K^T (warp: 16x64)
        float s[8][4];
#pragma unroll
        for (int nt = 0; nt < 8; nt++)
#pragma unroll
            for (int i = 0; i < 4; i++) s[nt][i] = 0.0f;

#pragma unroll
        for (int kk = 0; kk < 8; kk++) {
            const int fo = 8 * (kk ^ g) + tg * 2;    // swizzled frag col offset
            const float2 aA = *(const float2*)&Qs[(w16 + g) * 64 + fo];
            const float2 aB = *(const float2*)&Qs[(w16 + 8 + g) * 64 + fo];
#pragma unroll
            for (int nt = 0; nt < 8; nt++) {
                const float2 bv = *(const float2*)&Ksb[(nt * 8 + g) * 64 + fo];
                mma8(s[nt], aA.x, aB.x, aA.y, aB.y, bv.x, bv.y);
            }
        }

        // Mask (rare path)
        if (!g_mflag[blockIdx.x * 32 + kt]) {
            const int k0 = kt * 64;
            const int* mp0 = mask + (q0 + w16 + g) * S_ + k0 + tg * 2;
            const int* mp1 = mp0 + 8 * S_;
#pragma unroll
            for (int nt = 0; nt < 8; nt++) {
                const int2 m0v = *(const int2*)(mp0 + nt * 8);
                const int2 m1v = *(const int2*)(mp1 + nt * 8);
                if (m0v.x == 0) s[nt][0] = -1e9f;
                if (m0v.y == 0) s[nt][1] = -1e9f;
                if (m1v.x == 0) s[nt][2] = -1e9f;
                if (m1v.y == 0) s[nt][3] = -1e9f;
            }
        }

        // Online softmax (base 2); P stays in registers (s[])
        float mx0 = -1e30f, mx1 = -1e30f;
#pragma unroll
        for (int nt = 0; nt < 8; nt++) {
            mx0 = fmaxf(mx0, fmaxf(s[nt][0], s[nt][1]));
            mx1 = fmaxf(mx1, fmaxf(s[nt][2], s[nt][3]));
        }
        mx0 = fmaxf(mx0, __shfl_xor_sync(0xffffffffu, mx0, 1));
        mx0 = fmaxf(mx0, __shfl_xor_sync(0xffffffffu, mx0, 2));
        mx1 = fmaxf(mx1, __shfl_xor_sync(0xffffffffu, mx1, 1));
        mx1 = fmaxf(mx1, __shfl_xor_sync(0xffffffffu, mx1, 2));
        const float mn0 = fmaxf(mrow0, mx0);
        const float mn1 = fmaxf(mrow1, mx1);
        const float al0 = exp2f(mrow0 - mn0);
        const float al1 = exp2f(mrow1 - mn1);
        mrow0 = mn0; mrow1 = mn1;

        float sum0 = 0.0f, sum1 = 0.0f;
#pragma unroll
        for (int nt = 0; nt < 8; nt++) {
            const float p0 = exp2f(s[nt][0] - mn0);
            const float p1 = exp2f(s[nt][1] - mn0);
            const float p2 = exp2f(s[nt][2] - mn1);
            const float p3 = exp2f(s[nt][3] - mn1);
            sum0 += p0 + p1;
            sum1 += p2 + p3;
            s[nt][0] = to_tf32(p0);
            s[nt][1] = to_tf32(p1);
            s[nt][2] = to_tf32(p2);
            s[nt][3] = to_tf32(p3);
            o[nt][0] *= al0; o[nt][1] *= al0;
            o[nt][2] *= al1; o[nt][3] *= al1;
        }
        sum0 += __shfl_xor_sync(0xffffffffu, sum0, 1);
        sum0 += __shfl_xor_sync(0xffffffffu, sum0, 2);
        sum1 += __shfl_xor_sync(0xffffffffu, sum1, 1);
        sum1 += __shfl_xor_sync(0xffffffffu, sum1, 2);
        lrow0 = lrow0 * al0 + sum0;
        lrow1 = lrow1 * al1 + sum1;

        // O += P @ V (C-fragment reused as A-fragment; same k-permutation)
#pragma unroll
        for (int kk = 0; kk < 8; kk++) {
#pragma unroll
            for (int nt = 0; nt < 8; nt++) {
                const float2 bv =
                    *(const float2*)&Vtb[(nt * 8 + g) * 64 + 8 * (kk ^ g) + tg * 2];
                mma8(o[nt], s[kk][0], s[kk][2], s[kk][1], s[kk][3], bv.x, bv.y);
            }
        }

        __syncthreads();   // all warps done with stage (kt&1)
        KV_ISSUE(kt & 1, (kt + 2) & 31);   // wrap: last 2 iters load dead data
        CP_COMMIT();
    }
#undef KV_ISSUE

    CP_WAIT0();  // drain async copies before CTA exit

    // Normalize, round to tf32 (consumed via cp.async by oproj), store [B,S,D]
    const float inv0 = 1.0f / lrow0;
    const float inv1 = 1.0f / lrow1;
    const int bb = bh >> 4, h = bh & 15;
    const int r0 = q0 + w16 + g;
    float* O0 = &g_x[(bb * S_ + r0) * D_ + h * DK_ + tg * 2];
    float* O1 = O0 + 8 * D_;
#pragma unroll
    for (int nt = 0; nt < 8; nt++) {
        *(float2*)(O0 + nt * 8) =
            make_float2(to_tf32(o[nt][0] * inv0), to_tf32(o[nt][1] * inv0));
        *(float2*)(O1 + nt * 8) =
            make_float2(to_tf32(o[nt][2] * inv1), to_tf32(o[nt][3] * inv1));
    }
}

// ---------------------------------------------------------------------------
extern "C" void kernel_launch(void* const* d_in, const int* in_sizes, int n_in,
                              void* d_out, int out_size)
{
    (void)in_sizes; (void)n_in; (void)out_size;
    const float* q    = (const float*)d_in[0];
    const float* k    = (const float*)d_in[1];
    const float* v    = (const float*)d_in[2];
    const int*   mask = (const int*)d_in[3];
    const float* wq   = (const float*)d_in[4];
    const float* bq   = (const float*)d_in[5];
    const float* wk   = (const float*)d_in[6];
    const float* bk   = (const float*)d_in[7];
    const float* wv   = (const float*)d_in[8];
    const float* bv   = (const float*)d_in[9];
    const float* wo   = (const float*)d_in[10];
    const float* bo   = (const float*)d_in[11];
    float* out = (float*)d_out;

    static bool attrs_set = false;
    if (!attrs_set) {
        cudaFuncSetAttribute(qkv_kernel, cudaFuncAttributeMaxDynamicSharedMemorySize,
                             GEMM_SMEM_BYTES);
        cudaFuncSetAttribute(oproj_kernel, cudaFuncAttributeMaxDynamicSharedMemorySize,
                             GEMM_SMEM_BYTES);
        cudaFuncSetAttribute(attn_kernel, cudaFuncAttributeMaxDynamicSharedMemorySize,
                             ATTN_SMEM_BYTES);
        attrs_set = true;
    }

    // tf32 rounding prepass
    dim3 grd(1024, 7);
    round_kernel<<<grd, 256>>>(q, k, v, wq, wk, wv, wo);

    // QKV projections
    dim3 gqkv(D_ / 128, M_ / 128, 3);
    qkv_kernel<<<gqkv, 256, GEMM_SMEM_BYTES>>>(bq, bk, bv);

    // V transpose + mask prescan (independent, small)
    dim3 gvt(S_ / 32, DK_ / 32, B_ * H_);
    vtrans_kernel<<<gvt, 256>>>();
    dim3 gms(16, 32);
    mask_scan_kernel<<<gms, 256>>>(mask);

    // Attention
    dim3 gattn(S_ / 128, B_ * H_);
    attn_kernel<<<gattn, 256, ATTN_SMEM_BYTES>>>(mask);

    // Output projection
    dim3 gop(D_ / 128, M_ / 128);
    oproj_kernel<<<gop, 256, GEMM_SMEM_BYTES>>>(bo, out);
}